// round 16
// baseline (speedup 1.0000x reference)
#include <cuda_runtime.h>
#include <cuda_fp16.h>
#include <cstdint>

// ============================================================================
// 4D circular conv (3^4), implicit GEMM on mma.sync.m16n8k16.f32.f16.f16.f32,
// single fp16 chain (rel_err ~2.8e-4).
// R16: R15 (mixed full/half tile grid vs wave quantization) +
//  (1) ks loop fully unrolled -> ptxas pipelines LDSM across all 9 groups,
//  (2) prep_B/prep_X fused into one launch.
// ============================================================================

#define B_STRIDE 112      // bytes per co-row (56 f16; 48 used) -> conflict-free
#define B_BLK    7168     // 64 * 112
#define SMEM_BYTES 99840  // 2 x full-tile buffer (half tile uses less)
#define PLX 16777216      // elements per g_X plane (4*64*16^4)

__device__ __forceinline__ uint32_t smem_u32(const void* p) {
    uint32_t a;
    asm("{ .reg .u64 t; cvta.to.shared.u64 t, %1; cvt.u32.u64 %0, t; }" : "=r"(a) : "l"(p));
    return a;
}
__device__ __forceinline__ void cp16(uint32_t dst, const void* src) {
    asm volatile("cp.async.cg.shared.global [%0], [%1], 16;"
                 :: "r"(dst), "l"(__cvta_generic_to_global(src)) : "memory");
}
#define CP_COMMIT() asm volatile("cp.async.commit_group;" ::: "memory")
#define CP_WAIT(n)  asm volatile("cp.async.wait_group %0;" :: "n"(n) : "memory")

#define LDSM4(R, ADDR) \
    asm volatile("ldmatrix.sync.aligned.m8n8.x4.shared.b16 {%0,%1,%2,%3}, [%4];" \
        : "=r"((R)[0]), "=r"((R)[1]), "=r"((R)[2]), "=r"((R)[3]) : "r"(ADDR))
#define LDSM4T(R, ADDR) \
    asm volatile("ldmatrix.sync.aligned.m8n8.x4.trans.shared.b16 {%0,%1,%2,%3}, [%4];" \
        : "=r"((R)[0]), "=r"((R)[1]), "=r"((R)[2]), "=r"((R)[3]) : "r"(ADDR))
#define MMA16816(D, A, B0, B1) \
    asm volatile("mma.sync.aligned.m16n8k16.row.col.f32.f16.f16.f32 " \
        "{%0,%1,%2,%3}, {%4,%5,%6,%7}, {%8,%9}, {%0,%1,%2,%3};" \
        : "+f"((D)[0]), "+f"((D)[1]), "+f"((D)[2]), "+f"((D)[3]) \
        : "r"((A)[0]), "r"((A)[1]), "r"((A)[2]), "r"((A)[3]), "r"(B0), "r"(B1))

// ---- precomputed images -----------------------------------------------------
__device__ __align__(16) __half g_B[108 * 3584];        // [tap27,chunk4][co][k]
__device__ __align__(16) __half g_X[3u * PLX];          // [dw][b,ci,t,y,z][w]

// Fused prep: blocks 0..107 bake g_B; blocks 108.. bake g_X.
__global__ __launch_bounds__(256) void prep_all(
    const float* __restrict__ wt, const float* __restrict__ x)
{
    if (blockIdx.x < 108) {
        int nb = blockIdx.x;                   // ((i*3+dy)*3+dz)*4 + chunk
        int chunk = nb & 3, tap = nb >> 2;
        int dz = tap % 3, dy = (tap / 3) % 3, i = tap / 9;
        for (int e = threadIdx.x; e < 64 * 48; e += blockDim.x) {
            int co = e / 48, k = e - co * 48;  // k = cil*3 + dw
            int cil = k / 3, dw = k - cil * 3;
            int ci = chunk * 16 + cil;
            float w = wt[((i * 64 + co) * 64 + ci) * 27 + dy * 9 + dz * 3 + dw];
            g_B[nb * 3584 + co * 56 + k] = __float2half(w);
        }
        return;
    }
    // One thread per z-row (16 w floats): fp16 convert + 3 w-rotations.
    unsigned idx = (blockIdx.x - 108) * 256 + threadIdx.x;   // < 1048576
    const float4* src = (const float4*)(x + (size_t)idx * 16);
    float v[16];
    *(float4*)(v)      = src[0];
    *(float4*)(v + 4)  = src[1];
    *(float4*)(v + 8)  = src[2];
    *(float4*)(v + 12) = src[3];
    uint32_t hp[8];
#pragma unroll
    for (int j = 0; j < 8; j++) {
        __half h0 = __float2half(v[2 * j]), h1 = __float2half(v[2 * j + 1]);
        hp[j] = (uint32_t)__half_as_ushort(h0) | ((uint32_t)__half_as_ushort(h1) << 16);
    }
    uint32_t h0r[8], h2r[8];
#pragma unroll
    for (int j = 0; j < 8; j++) {
        h0r[j] = __byte_perm(hp[(j + 7) & 7], hp[j], 0x5432);   // x[(w-1) mod 16]
        h2r[j] = __byte_perm(hp[j], hp[(j + 1) & 7], 0x5432);   // x[(w+1) mod 16]
    }
    size_t ro = (size_t)idx * 16;
    uint4* p0 = (uint4*)(g_X + 0 * (size_t)PLX + ro);   // dw0
    uint4* p1 = (uint4*)(g_X + 1 * (size_t)PLX + ro);   // dw1
    uint4* p2 = (uint4*)(g_X + 2 * (size_t)PLX + ro);   // dw2
    p0[0] = make_uint4(h0r[0], h0r[1], h0r[2], h0r[3]);
    p0[1] = make_uint4(h0r[4], h0r[5], h0r[6], h0r[7]);
    p1[0] = make_uint4(hp[0], hp[1], hp[2], hp[3]);
    p1[1] = make_uint4(hp[4], hp[5], hp[6], hp[7]);
    p2[0] = make_uint4(h2r[0], h2r[1], h2r[2], h2r[3]);
    p2[1] = make_uint4(h2r[4], h2r[5], h2r[6], h2r[7]);
}

// ---- templated tile body: MI m-fragments per warp (4=full M256, 2=half M128),
//      AS = A k-row stride in bytes ---------------------------------------
template <int MI, int AS>
__device__ __forceinline__ void conv_tile(
    int b, int t, int y, int zbase,
    const float* __restrict__ bias, float* __restrict__ out,
    char* smem, uint32_t sb, int tid)
{
    constexpr int OFFB = 48 * AS;
    constexpr int BUF  = OFFB + 3 * B_BLK;
    constexpr int ZR   = MI * 4 + 2;          // halo z-rows: 18 or 10
    const int l = tid & 31, wm = tid >> 5;

    const uint32_t aoff = ((l & 7) + ((l >> 4) & 1) * 8) * AS + ((l >> 3) & 1) * 16;
    const uint32_t boff = ((l & 7) + ((l >> 4) & 1) * 8) * B_STRIDE + ((l >> 3) & 1) * 16;

    float d[MI][8][4];
#pragma unroll
    for (int mi = 0; mi < MI; mi++)
#pragma unroll
        for (int nj = 0; nj < 8; nj++)
#pragma unroll
            for (int e = 0; e < 4; e++) d[mi][nj][e] = 0.f;

    auto stage = [&](uint32_t sbuf, int p) {
        const int chunk = p & 3;
        const int idy9 = p >> 2;
        const int i = idy9 / 3, dy = idy9 - i * 3;
        const int tt = (t + i + 15) & 15;
        const int yy = (y + dy + 15) & 15;
        const size_t cb = ((size_t)(b * 64 + chunk * 16) << 16) + tt * 4096 + yy * 256;
        for (int idx = tid; idx < 48 * ZR; idx += 128) {
            int krow = idx / ZR, r = idx - krow * ZR;   // krow = cil*3 + dw
            int cil = krow / 3, dw = krow - cil * 3;
            int z_in = (zbase + 15 + r) & 15;
            size_t so = (size_t)dw * PLX + cb + ((size_t)cil << 16) + z_in * 16;
            uint32_t dst = sbuf + krow * AS + r * 32;
            cp16(dst,      g_X + so);
            cp16(dst + 16, g_X + so + 8);
        }
        const int tapb = idy9 * 3;
        for (int q = tid; q < 1344; q += 128) {
            int s = q / 448, r = q - s * 448;
            int nb = ((tapb + s) << 2) + chunk;
            cp16(sbuf + OFFB + s * B_BLK + r * 16,
                 (const char*)g_B + (size_t)nb * B_BLK + r * 16);
        }
    };

    stage(sb, 0);
    CP_COMMIT();

#pragma unroll 1
    for (int p = 0; p < 36; p++) {
        if (p < 35) {
            stage(sb + ((p + 1) & 1) * BUF, p + 1);
            CP_COMMIT();
            CP_WAIT(1);
        } else {
            CP_WAIT(0);
        }
        __syncthreads();

        const uint32_t cbuf = sb + (p & 1) * BUF;
        // Fully unrolled 9 (ks,dz) groups: ptxas pipelines LDSM across groups.
#pragma unroll
        for (int ks = 0; ks < 3; ks++) {
#pragma unroll
            for (int dz = 0; dz < 3; dz++) {
                uint32_t a[MI][4], bv[4][4];
                uint32_t ab = cbuf + ks * (16 * AS) + dz * 32 + wm * (MI * 32) + aoff;
#pragma unroll
                for (int c = 0; c < MI; c++) LDSM4T(a[c], ab + c * 32);
                uint32_t bb = cbuf + OFFB + dz * B_BLK + ks * 32 + boff;
                LDSM4(bv[0], bb);
                LDSM4(bv[1], bb + 16 * B_STRIDE);
                LDSM4(bv[2], bb + 32 * B_STRIDE);
                LDSM4(bv[3], bb + 48 * B_STRIDE);
#pragma unroll
                for (int mi = 0; mi < MI; mi++)
#pragma unroll
                    for (int nj = 0; nj < 8; nj++) {
                        uint32_t* bp = &bv[nj >> 1][(nj & 1) * 2];
                        MMA16816(d[mi][nj], a[mi], bp[0], bp[1]);
                    }
            }
        }
        __syncthreads();
    }

    // ---- epilogue: transpose through SMEM, coalesced float4 stores ----
    float* sf = (float*)smem;                  // [co][260] f32
#pragma unroll
    for (int mi = 0; mi < MI; mi++)
#pragma unroll
        for (int nj = 0; nj < 8; nj++) {
            int r = l >> 2, c = (l & 3) * 2;
            int m0 = wm * (MI * 16) + mi * 16;
            int co = nj * 8 + c;
            sf[co * 260 + m0 + r]           = d[mi][nj][0];
            sf[(co + 1) * 260 + m0 + r]     = d[mi][nj][1];
            sf[co * 260 + m0 + r + 8]       = d[mi][nj][2];
            sf[(co + 1) * 260 + m0 + r + 8] = d[mi][nj][3];
        }
    __syncthreads();
    const int pbase = (t * 16 + y) * 256 + zbase * 16;
    for (int q = tid; q < MI * 1024; q += 128) {
        int co = q / (MI * 16), c = (q & (MI * 16 - 1)) * 4;
        float4 v = *(float4*)&sf[co * 260 + c];
        float bv = __ldg(bias + co);
        v.x += bv; v.y += bv; v.z += bv; v.w += bv;
        *(float4*)(out + (((size_t)(b * 64 + co)) << 16) + pbase + c) = v;
    }
}

// ---- main kernel ------------------------------------------------------------
__global__ __launch_bounds__(128, 2) void conv4d_mma(
    const float* __restrict__ bias, float* __restrict__ out)
{
    extern __shared__ __align__(16) char smem[];
    const uint32_t sb = smem_u32(smem);
    const int tid = threadIdx.x;
    const int bid = blockIdx.x;

    if (bid < 896) {                           // full tiles 0..895 (M=256)
        int y = bid & 15, t = (bid >> 4) & 15, b = bid >> 8;
        conv_tile<4, 592>(b, t, y, 0, bias, out, smem, sb, tid);
    } else {                                   // tiles 896..1023 as 2 z-halves
        int j = bid - 896;
        int tile = 896 + (j >> 1), h = j & 1;
        int y = tile & 15, t = (tile >> 4) & 15, b = tile >> 8;
        conv_tile<2, 336>(b, t, y, 8 * h, bias, out, smem, sb, tid);
    }
}

extern "C" void kernel_launch(void* const* d_in, const int* in_sizes, int n_in,
                              void* d_out, int out_size) {
    const float* x    = (const float*)d_in[0];
    const float* wt   = (const float*)d_in[1];
    const float* bias = (const float*)d_in[2];
    float* out        = (float*)d_out;

    cudaFuncSetAttribute(conv4d_mma, cudaFuncAttributeMaxDynamicSharedMemorySize, SMEM_BYTES);
    prep_all<<<108 + 4096, 256>>>(wt, x);
    conv4d_mma<<<1152, 128, SMEM_BYTES>>>(bias, out);
}

// round 17
// speedup vs baseline: 1.0759x; 1.0759x over previous
#include <cuda_runtime.h>
#include <cuda_fp16.h>
#include <cstdint>

// ============================================================================
// 4D circular conv (3^4), implicit GEMM on mma.sync.m16n8k16.f32.f16.f16.f32,
// single fp16 chain (rel_err ~2.8e-4).
// R17: R15 base (mixed full/half tiles, ks unroll 1) + phase-invariant staging
// addresses hoisted into per-thread register tables (only 2 scalars vary per
// phase), removing ~75% of the staging ALU from the critical path.
// ============================================================================

#define B_STRIDE 112      // bytes per co-row (56 f16; 48 used) -> conflict-free
#define B_BLK    7168     // 64 * 112
#define SMEM_BYTES 99840  // 2 x full-tile buffer (half tile uses less)
#define PLX 16777216      // elements per g_X plane (4*64*16^4)

__device__ __forceinline__ uint32_t smem_u32(const void* p) {
    uint32_t a;
    asm("{ .reg .u64 t; cvta.to.shared.u64 t, %1; cvt.u32.u64 %0, t; }" : "=r"(a) : "l"(p));
    return a;
}
__device__ __forceinline__ void cp16(uint32_t dst, const void* src) {
    asm volatile("cp.async.cg.shared.global [%0], [%1], 16;"
                 :: "r"(dst), "l"(__cvta_generic_to_global(src)) : "memory");
}
#define CP_COMMIT() asm volatile("cp.async.commit_group;" ::: "memory")
#define CP_WAIT(n)  asm volatile("cp.async.wait_group %0;" :: "n"(n) : "memory")

#define LDSM4(R, ADDR) \
    asm volatile("ldmatrix.sync.aligned.m8n8.x4.shared.b16 {%0,%1,%2,%3}, [%4];" \
        : "=r"((R)[0]), "=r"((R)[1]), "=r"((R)[2]), "=r"((R)[3]) : "r"(ADDR))
#define LDSM4T(R, ADDR) \
    asm volatile("ldmatrix.sync.aligned.m8n8.x4.trans.shared.b16 {%0,%1,%2,%3}, [%4];" \
        : "=r"((R)[0]), "=r"((R)[1]), "=r"((R)[2]), "=r"((R)[3]) : "r"(ADDR))
#define MMA16816(D, A, B0, B1) \
    asm volatile("mma.sync.aligned.m16n8k16.row.col.f32.f16.f16.f32 " \
        "{%0,%1,%2,%3}, {%4,%5,%6,%7}, {%8,%9}, {%0,%1,%2,%3};" \
        : "+f"((D)[0]), "+f"((D)[1]), "+f"((D)[2]), "+f"((D)[3]) \
        : "r"((A)[0]), "r"((A)[1]), "r"((A)[2]), "r"((A)[3]), "r"(B0), "r"(B1))

// ---- precomputed images -----------------------------------------------------
__device__ __align__(16) __half g_B[108 * 3584];        // [tap27,chunk4][co][k]
__device__ __align__(16) __half g_X[3u * PLX];          // [dw][b,ci,t,y,z][w]

// Fused prep: blocks 0..107 bake g_B; blocks 108.. bake g_X.
__global__ __launch_bounds__(256) void prep_all(
    const float* __restrict__ wt, const float* __restrict__ x)
{
    if (blockIdx.x < 108) {
        int nb = blockIdx.x;                   // ((i*3+dy)*3+dz)*4 + chunk
        int chunk = nb & 3, tap = nb >> 2;
        int dz = tap % 3, dy = (tap / 3) % 3, i = tap / 9;
        for (int e = threadIdx.x; e < 64 * 48; e += blockDim.x) {
            int co = e / 48, k = e - co * 48;  // k = cil*3 + dw
            int cil = k / 3, dw = k - cil * 3;
            int ci = chunk * 16 + cil;
            float w = wt[((i * 64 + co) * 64 + ci) * 27 + dy * 9 + dz * 3 + dw];
            g_B[nb * 3584 + co * 56 + k] = __float2half(w);
        }
        return;
    }
    unsigned idx = (blockIdx.x - 108) * 256 + threadIdx.x;   // < 1048576
    const float4* src = (const float4*)(x + (size_t)idx * 16);
    float v[16];
    *(float4*)(v)      = src[0];
    *(float4*)(v + 4)  = src[1];
    *(float4*)(v + 8)  = src[2];
    *(float4*)(v + 12) = src[3];
    uint32_t hp[8];
#pragma unroll
    for (int j = 0; j < 8; j++) {
        __half h0 = __float2half(v[2 * j]), h1 = __float2half(v[2 * j + 1]);
        hp[j] = (uint32_t)__half_as_ushort(h0) | ((uint32_t)__half_as_ushort(h1) << 16);
    }
    uint32_t h0r[8], h2r[8];
#pragma unroll
    for (int j = 0; j < 8; j++) {
        h0r[j] = __byte_perm(hp[(j + 7) & 7], hp[j], 0x5432);   // x[(w-1) mod 16]
        h2r[j] = __byte_perm(hp[j], hp[(j + 1) & 7], 0x5432);   // x[(w+1) mod 16]
    }
    size_t ro = (size_t)idx * 16;
    uint4* p0 = (uint4*)(g_X + 0 * (size_t)PLX + ro);   // dw0
    uint4* p1 = (uint4*)(g_X + 1 * (size_t)PLX + ro);   // dw1
    uint4* p2 = (uint4*)(g_X + 2 * (size_t)PLX + ro);   // dw2
    p0[0] = make_uint4(h0r[0], h0r[1], h0r[2], h0r[3]);
    p0[1] = make_uint4(h0r[4], h0r[5], h0r[6], h0r[7]);
    p1[0] = make_uint4(hp[0], hp[1], hp[2], hp[3]);
    p1[1] = make_uint4(hp[4], hp[5], hp[6], hp[7]);
    p2[0] = make_uint4(h2r[0], h2r[1], h2r[2], h2r[3]);
    p2[1] = make_uint4(h2r[4], h2r[5], h2r[6], h2r[7]);
}

// ---- templated tile body: MI m-fragments per warp (4=full M256, 2=half M128),
//      AS = A k-row stride in bytes ---------------------------------------
template <int MI, int AS>
__device__ __forceinline__ void conv_tile(
    int b, int t, int y, int zbase,
    const float* __restrict__ bias, float* __restrict__ out,
    char* smem, uint32_t sb, int tid)
{
    constexpr int OFFB = 48 * AS;
    constexpr int BUF  = OFFB + 3 * B_BLK;
    constexpr int ZR   = MI * 4 + 2;              // halo z-rows: 18 or 10
    constexpr int NA   = (48 * ZR + 127) / 128;   // 7 (full) or 4 (half)
    constexpr int ATAIL = 48 * ZR - (NA - 1) * 128;
    constexpr int NB   = 11;                      // ceil(1344/128)
    const int l = tid & 31, wm = tid >> 5;

    const uint32_t aoff = ((l & 7) + ((l >> 4) & 1) * 8) * AS + ((l >> 3) & 1) * 16;
    const uint32_t boff = ((l & 7) + ((l >> 4) & 1) * 8) * B_STRIDE + ((l >> 3) & 1) * 16;

    // ---- phase-invariant staging address tables (registers) ----
    uint32_t a_dst[NA], a_src[NA];                // a_src in g_X ELEMENTS
#pragma unroll
    for (int it = 0; it < NA; it++) {
        int idx = tid + it * 128;
        if (it < NA - 1 || tid < ATAIL) {
            int krow = idx / ZR, r = idx - krow * ZR;   // krow = cil*3 + dw
            int cil = krow / 3, dw = krow - cil * 3;
            int z_in = (zbase + 15 + r) & 15;
            a_src[it] = (uint32_t)dw * PLX + ((uint32_t)cil << 16) + z_in * 16;
            a_dst[it] = krow * AS + r * 32;
        } else { a_dst[it] = 0; a_src[it] = 0; }
    }
    uint32_t b_dst[NB], b_src[NB];                // b_src in g_B BYTES
#pragma unroll
    for (int it = 0; it < NB; it++) {
        int q = tid + it * 128;
        if (it < NB - 1 || tid < 1344 - (NB - 1) * 128) {
            int s = q / 448, r = q - s * 448;
            b_src[it] = (uint32_t)(s * 4) * B_BLK + r * 16;
            b_dst[it] = OFFB + s * B_BLK + r * 16;
        } else { b_dst[it] = 0; b_src[it] = 0; }
    }

    float d[MI][8][4];
#pragma unroll
    for (int mi = 0; mi < MI; mi++)
#pragma unroll
        for (int nj = 0; nj < 8; nj++)
#pragma unroll
            for (int e = 0; e < 4; e++) d[mi][nj][e] = 0.f;

    auto stage = [&](uint32_t sbuf, int p) {
        const int chunk = p & 3;
        const int idy9 = p >> 2;
        const int i = idy9 / 3, dy = idy9 - i * 3;
        const int tt = (t + i + 15) & 15;
        const int yy = (y + dy + 15) & 15;
        const uint32_t cb = ((uint32_t)(b * 64 + chunk * 16) << 16) + tt * 4096 + yy * 256;
#pragma unroll
        for (int it = 0; it < NA; it++) {
            if (it < NA - 1 || tid < ATAIL) {
                const __half* s = g_X + (size_t)(a_src[it] + cb);
                cp16(sbuf + a_dst[it], s);
                cp16(sbuf + a_dst[it] + 16, s + 8);
            }
        }
        const uint32_t bphase = (uint32_t)(idy9 * 12 + chunk) * B_BLK;  // (tapb*4+chunk)*B_BLK
#pragma unroll
        for (int it = 0; it < NB; it++) {
            if (it < NB - 1 || tid < 1344 - (NB - 1) * 128) {
                cp16(sbuf + b_dst[it], (const char*)g_B + (b_src[it] + bphase));
            }
        }
    };

    stage(sb, 0);
    CP_COMMIT();

#pragma unroll 1
    for (int p = 0; p < 36; p++) {
        if (p < 35) {
            stage(sb + ((p + 1) & 1) * BUF, p + 1);
            CP_COMMIT();
            CP_WAIT(1);
        } else {
            CP_WAIT(0);
        }
        __syncthreads();

        const uint32_t cbuf = sb + (p & 1) * BUF;
#pragma unroll 1
        for (int ks = 0; ks < 3; ks++) {
#pragma unroll
            for (int dz = 0; dz < 3; dz++) {
                uint32_t a[MI][4], bv[4][4];
                uint32_t ab = cbuf + ks * (16 * AS) + dz * 32 + wm * (MI * 32) + aoff;
#pragma unroll
                for (int c = 0; c < MI; c++) LDSM4T(a[c], ab + c * 32);
                uint32_t bb = cbuf + OFFB + dz * B_BLK + ks * 32 + boff;
                LDSM4(bv[0], bb);
                LDSM4(bv[1], bb + 16 * B_STRIDE);
                LDSM4(bv[2], bb + 32 * B_STRIDE);
                LDSM4(bv[3], bb + 48 * B_STRIDE);
#pragma unroll
                for (int mi = 0; mi < MI; mi++)
#pragma unroll
                    for (int nj = 0; nj < 8; nj++) {
                        uint32_t* bp = &bv[nj >> 1][(nj & 1) * 2];
                        MMA16816(d[mi][nj], a[mi], bp[0], bp[1]);
                    }
            }
        }
        __syncthreads();
    }

    // ---- epilogue: transpose through SMEM, coalesced float4 stores ----
    float* sf = (float*)smem;                  // [co][260] f32
#pragma unroll
    for (int mi = 0; mi < MI; mi++)
#pragma unroll
        for (int nj = 0; nj < 8; nj++) {
            int r = l >> 2, c = (l & 3) * 2;
            int m0 = wm * (MI * 16) + mi * 16;
            int co = nj * 8 + c;
            sf[co * 260 + m0 + r]           = d[mi][nj][0];
            sf[(co + 1) * 260 + m0 + r]     = d[mi][nj][1];
            sf[co * 260 + m0 + r + 8]       = d[mi][nj][2];
            sf[(co + 1) * 260 + m0 + r + 8] = d[mi][nj][3];
        }
    __syncthreads();
    const int pbase = (t * 16 + y) * 256 + zbase * 16;
    for (int q = tid; q < MI * 1024; q += 128) {
        int co = q / (MI * 16), c = (q & (MI * 16 - 1)) * 4;
        float4 v = *(float4*)&sf[co * 260 + c];
        float bv = __ldg(bias + co);
        v.x += bv; v.y += bv; v.z += bv; v.w += bv;
        *(float4*)(out + (((size_t)(b * 64 + co)) << 16) + pbase + c) = v;
    }
}

// ---- main kernel ------------------------------------------------------------
__global__ __launch_bounds__(128, 2) void conv4d_mma(
    const float* __restrict__ bias, float* __restrict__ out)
{
    extern __shared__ __align__(16) char smem[];
    const uint32_t sb = smem_u32(smem);
    const int tid = threadIdx.x;
    const int bid = blockIdx.x;

    if (bid < 896) {                           // full tiles 0..895 (M=256)
        int y = bid & 15, t = (bid >> 4) & 15, b = bid >> 8;
        conv_tile<4, 592>(b, t, y, 0, bias, out, smem, sb, tid);
    } else {                                   // tiles 896..1023 as 2 z-halves
        int j = bid - 896;
        int tile = 896 + (j >> 1), h = j & 1;
        int y = tile & 15, t = (tile >> 4) & 15, b = tile >> 8;
        conv_tile<2, 336>(b, t, y, 8 * h, bias, out, smem, sb, tid);
    }
}

extern "C" void kernel_launch(void* const* d_in, const int* in_sizes, int n_in,
                              void* d_out, int out_size) {
    const float* x    = (const float*)d_in[0];
    const float* wt   = (const float*)d_in[1];
    const float* bias = (const float*)d_in[2];
    float* out        = (float*)d_out;

    cudaFuncSetAttribute(conv4d_mma, cudaFuncAttributeMaxDynamicSharedMemorySize, SMEM_BYTES);
    prep_all<<<108 + 4096, 256>>>(wt, x);
    conv4d_mma<<<1152, 128, SMEM_BYTES>>>(bias, out);
}